// round 17
// baseline (speedup 1.0000x reference)
#include <cuda_runtime.h>
#include <cstdint>

#define T_LEN  4096
#define NTH    256
#define PER    4                  // steps per thread
#define SPLIT  4                  // tiles per sequence
#define TILE_STEPS (NTH * PER)    // 1024

#define DTF    (1.0f / 200.0f)
#define DT2H   (DTF * DTF * 0.5f)
#define STEPDT ((float)PER * DTF)

#define MAX_SEQ 1024

// dynamic smem partition (floats)
#define S_IN_OFF    0
#define S_IN_SIZE   9248          // rows (k*257+tid) <= 1026, *9 floats
#define S_OUT_OFF   (S_IN_OFF + S_IN_SIZE)
#define S_OUT_SIZE  (16 * 257)    // 1-step output staging: 16 channels x 257 pitch
#define S_W_OFF     (S_OUT_OFF + S_OUT_SIZE)
#define S_W_SIZE    (8 * 11)
#define S_PRE_OFF   (S_W_OFF + S_W_SIZE)
#define S_PRE_SIZE  (SPLIT * 10)
#define S_PREV_OFF  (S_PRE_OFF + S_PRE_SIZE)
#define S_PREV_SIZE 10
#define SMEM_FLOATS (S_PREV_OFF + S_PREV_SIZE + 6)
#define SMEM_BYTES  (SMEM_FLOATS * 4)

// cross-tile exchange buffers. flags are zero-initialized at module load and
// reset to zero by the LAST reader each launch -> no clearing kernel needed.
__device__ float g_agg[MAX_SEQ * SPLIT * 10];
__device__ int   g_flags[MAX_SEQ * SPLIT];

// scan element: unit quaternion q, v, p.
struct QC { float qw,qx,qy,qz, vx,vy,vz, px,py,pz; };

__device__ __forceinline__ void set_identity(QC& C) {
    C.qw=1.f; C.qx=0.f; C.qy=0.f; C.qz=0.f;
    C.vx=C.vy=C.vz=0.f; C.px=C.py=C.pz=0.f;
}

__device__ __forceinline__ void rot_q(float qw,float qx,float qy,float qz,
                                      float x,float y,float z,
                                      float& rx,float& ry,float& rz) {
    float tx = 2.0f*(qy*z - qz*y);
    float ty = 2.0f*(qz*x - qx*z);
    float tz = 2.0f*(qx*y - qy*x);
    rx = x + qw*tx + (qy*tz - qz*ty);
    ry = y + qw*ty + (qz*tx - qx*tz);
    rz = z + qw*tz + (qx*ty - qy*tx);
}

// C = L compose C (L earlier); span_r = time span covered by C
__device__ __forceinline__ void compose_left(QC& C, const QC& L, float span_r) {
    float qw = L.qw*C.qw - L.qx*C.qx - L.qy*C.qy - L.qz*C.qz;
    float qx = L.qw*C.qx + L.qx*C.qw + L.qy*C.qz - L.qz*C.qy;
    float qy = L.qw*C.qy - L.qx*C.qz + L.qy*C.qw + L.qz*C.qx;
    float qz = L.qw*C.qz + L.qx*C.qy - L.qy*C.qx + L.qz*C.qw;
    float rvx,rvy,rvz; rot_q(L.qw,L.qx,L.qy,L.qz, C.vx,C.vy,C.vz, rvx,rvy,rvz);
    float rpx,rpy,rpz; rot_q(L.qw,L.qx,L.qy,L.qz, C.px,C.py,C.pz, rpx,rpy,rpz);
    C.qw=qw; C.qx=qx; C.qy=qy; C.qz=qz;
    C.vx = L.vx + rvx;  C.vy = L.vy + rvy;  C.vz = L.vz + rvz;
    C.px = L.px + L.vx*span_r + rpx;
    C.py = L.py + L.vy*span_r + rpy;
    C.pz = L.pz + L.vz*span_r + rpz;
}

__device__ __forceinline__ void step_q(QC& C, float wx,float wy,float wz,
                                       float ax,float ay,float az) {
    float n2 = fmaf(wx,wx, fmaf(wy,wy, wz*wz));
    float h2 = n2 * (0.25f * DTF * DTF);
    float dqw = 1.0f - h2*(0.5f - h2*(1.0f/24.0f));
    float s   = (0.5f*DTF) * (1.0f - h2*(1.0f/6.0f - h2*(1.0f/120.0f)));
    float dqx = wx*s, dqy = wy*s, dqz = wz*s;

    float qw = C.qw*dqw - C.qx*dqx - C.qy*dqy - C.qz*dqz;
    float qx = C.qw*dqx + C.qx*dqw + C.qy*dqz - C.qz*dqy;
    float qy = C.qw*dqy - C.qx*dqz + C.qy*dqw + C.qz*dqx;
    float qz = C.qw*dqz + C.qx*dqy - C.qy*dqx + C.qz*dqw;
    C.qw=qw; C.qx=qx; C.qy=qy; C.qz=qz;

    float Rax,Ray,Raz; rot_q(qw,qx,qy,qz, ax,ay,az, Rax,Ray,Raz);

    C.vx += Rax*DTF; C.vy += Ray*DTF; C.vz += Raz*DTF;
    C.px += C.vx*DTF + Rax*DT2H;
    C.py += C.vy*DTF + Ray*DT2H;
    C.pz += C.vz*DTF + Raz*DT2H;
}

__device__ __forceinline__ QC shup(const QC& c, int d) {
    QC r;
    r.qw=__shfl_up_sync(0xffffffffu,c.qw,d);
    r.qx=__shfl_up_sync(0xffffffffu,c.qx,d);
    r.qy=__shfl_up_sync(0xffffffffu,c.qy,d);
    r.qz=__shfl_up_sync(0xffffffffu,c.qz,d);
    r.vx=__shfl_up_sync(0xffffffffu,c.vx,d);
    r.vy=__shfl_up_sync(0xffffffffu,c.vy,d);
    r.vz=__shfl_up_sync(0xffffffffu,c.vz,d);
    r.px=__shfl_up_sync(0xffffffffu,c.px,d);
    r.py=__shfl_up_sync(0xffffffffu,c.py,d);
    r.pz=__shfl_up_sync(0xffffffffu,c.pz,d);
    return r;
}

__device__ __forceinline__ void store_qc(float* m, const QC& C) {
    m[0]=C.qw; m[1]=C.qx; m[2]=C.qy; m[3]=C.qz;
    m[4]=C.vx; m[5]=C.vy; m[6]=C.vz;
    m[7]=C.px; m[8]=C.py; m[9]=C.pz;
}
__device__ __forceinline__ void load_qc(const float* m, QC& C) {
    C.qw=m[0]; C.qx=m[1]; C.qy=m[2]; C.qz=m[3];
    C.vx=m[4]; C.vy=m[5]; C.vz=m[6];
    C.px=m[7]; C.py=m[8]; C.pz=m[9];
}

// step s (0..1023) -> staging row; lane-stride on read = 9 floats (conflict-free)
__device__ __forceinline__ int in_row(int s) { return (s & 3) * 257 + (s >> 2); }

__global__ void __launch_bounds__(NTH, 4)
preint_kernel(const float* __restrict__ in, float* __restrict__ out) {
    extern __shared__ float sm[];
    float* s_in   = sm + S_IN_OFF;
    float* s_out  = sm + S_OUT_OFF;
    float* s_w    = sm + S_W_OFF;
    float* s_pre  = sm + S_PRE_OFF;
    float* s_prev = sm + S_PREV_OFF;

    const int tid  = threadIdx.x;
    const int lane = tid & 31;
    const int wid  = tid >> 5;
    const int seq  = blockIdx.x >> 2;     // sequence index
    const int rr   = blockIdx.x & 3;      // tile rank within sequence
    const int gidx = seq * SPLIT + rr;

    // ---------------- Coalesced load of the whole tile into transposed smem ----------------
    const float4* in4 = (const float4*)in
        + ((size_t)seq * (T_LEN * 6) + (size_t)rr * (TILE_STEPS * 6)) / 4;
#pragma unroll
    for (int r = 0; r < 6; r++) {
        int G = r * NTH + tid;            // fully coalesced float4 index
        float4 v = __ldg(in4 + G);
        float vv[4] = {v.x, v.y, v.z, v.w};
        int F = G * 4;
#pragma unroll
        for (int j = 0; j < 4; j++) {
            int Fj = F + j;
            int s  = Fj / 6;              // step within tile
            int c  = Fj - s * 6;          // channel 0..5
            s_in[in_row(s) * 9 + c] = vv[j];
        }
    }
    __syncthreads();

    // ---------------- Phase 1: two independent 2-step chains, then merge (ILP x2) ----------
    float X[4][6];
#pragma unroll
    for (int k = 0; k < 4; k++) {
        int base = (k * 257 + tid) * 9;
#pragma unroll
        for (int c = 0; c < 6; c++) X[k][c] = s_in[base + c];
    }
    QC C, C2;
    set_identity(C);
    set_identity(C2);
    step_q(C,  X[0][0], X[0][1], X[0][2], X[0][3], X[0][4], X[0][5]);
    step_q(C2, X[2][0], X[2][1], X[2][2], X[2][3], X[2][4], X[2][5]);
    step_q(C,  X[1][0], X[1][1], X[1][2], X[1][3], X[1][4], X[1][5]);
    step_q(C2, X[3][0], X[3][1], X[3][2], X[3][3], X[3][4], X[3][5]);
    compose_left(C2, C, 2.0f * DTF);      // A (earlier) o B (later)
    C = C2;

    // ---------------- Intra-warp inclusive scan (shuffles) ----------------
#pragma unroll
    for (int dd = 1; dd < 32; dd <<= 1) {
        QC L = shup(C, dd);
        if (lane >= dd) compose_left(C, L, (float)dd * STEPDT);
    }
    if (lane == 31) store_qc(s_w + wid * 11, C);
    __syncthreads();

    // ---------------- Inter-warp scan (warp 0) || flattened look-back (warp 1) -------------
    if (wid == 0) {
        QC A;
        if (lane < 8) load_qc(s_w + lane * 11, A);
        else          set_identity(A);
#pragma unroll
        for (int dd = 1; dd < 8; dd <<= 1) {
            QC L = shup(A, dd);
            if (lane >= dd && lane < 8) compose_left(A, L, (float)(dd * 32) * STEPDT);
        }
        if (lane < 8) store_qc(s_w + lane * 11, A);
        // publish tile-LOCAL total (lane 7 holds it) immediately — no forwarding chain
        if (lane == 7 && rr != SPLIT - 1) {
            float* dst = g_agg + (size_t)gidx * 10;
            store_qc(dst, A);
            __threadfence();
            atomicExch(&g_flags[gidx], 1);
        }
    } else if (wid == 1) {
        // lanes 0..rr-1 each poll ONE predecessor in parallel (no chain)
        if (lane < rr) {
            int  src  = seq * SPLIT + lane;
            int* flag = &g_flags[src];
            while (atomicAdd(flag, 0) == 0) { __nanosleep(32); }
            __threadfence();
            const float* sp = g_agg + (size_t)src * 10;
#pragma unroll
            for (int i = 0; i < 10; i++) s_pre[lane * 10 + i] = sp[i];
            // last-reader reset: flag of rank `lane` has SPLIT-1-lane readers
            int old = atomicAdd(flag, 1);
            if (old == SPLIT - 1 - lane) atomicExch(flag, 0);
        }
        __syncwarp();
        if (lane == 0 && rr > 0) {
            QC P;
            load_qc(s_pre + (rr - 1) * 10, P);          // latest predecessor
            for (int j = rr - 2; j >= 0; j--) {
                QC L; load_qc(s_pre + j * 10, L);
                compose_left(P, L, (float)(rr - 1 - j) * TILE_STEPS * DTF);
            }
            store_qc(s_prev, P);
        }
    }
    __syncthreads();

    // ---------------- Per-thread exclusive prefix (within tile, then global) --------------
    {
        QC E = shup(C, 1);
        if (lane == 0) set_identity(E);
        QC W;
        if (wid == 0) set_identity(W);
        else          load_qc(s_w + (wid - 1) * 11, W);
        compose_left(E, W, (float)(lane * PER) * DTF);
        if (rr > 0) {
            QC P; load_qc(s_prev, P);
            compose_left(E, P, (float)(tid * PER) * DTF);
        }
        C = E;
    }

    // ---------------- Phase 2: replay from smem, per-step staged + coalesced output --------
    float4* out4 = (float4*)out
        + (size_t)seq * (T_LEN * 4) + (size_t)rr * (TILE_STEPS * 4);

#pragma unroll
    for (int k = 0; k < 4; k++) {
        int base = (k * 257 + tid) * 9;
        float wx = s_in[base + 0], wy = s_in[base + 1], wz = s_in[base + 2];
        float ax = s_in[base + 3], ay = s_in[base + 4], az = s_in[base + 5];

        step_q(C, wx, wy, wz, ax, ay, az);

        // output quaternion = carry, renormalized, sign-fixed (qw >= 0)
        float n  = fmaf(C.qw,C.qw, fmaf(C.qx,C.qx, fmaf(C.qy,C.qy, C.qz*C.qz)));
        float rn = rsqrtf(n);
        rn = (C.qw < 0.0f) ? -rn : rn;
        float qw = C.qw*rn, qx = C.qx*rn, qy = C.qy*rn, qz = C.qz*rn;

        // stage 16 channels at column tid (conflict-free: pitch 257)
        s_out[ 0*257 + tid] = wx;   s_out[ 1*257 + tid] = wy;
        s_out[ 2*257 + tid] = wz;   s_out[ 3*257 + tid] = ax;
        s_out[ 4*257 + tid] = ay;   s_out[ 5*257 + tid] = az;
        s_out[ 6*257 + tid] = C.px; s_out[ 7*257 + tid] = C.py;
        s_out[ 8*257 + tid] = C.pz; s_out[ 9*257 + tid] = qw;
        s_out[10*257 + tid] = qx;   s_out[11*257 + tid] = qy;
        s_out[12*257 + tid] = qz;   s_out[13*257 + tid] = C.vx;
        s_out[14*257 + tid] = C.vy; s_out[15*257 + tid] = C.vz;
        __syncthreads();

        // coalesced flush: 1 step x 256 owners = 1024 float4, 4 per thread
#pragma unroll
        for (int r = 0; r < 4; r++) {
            int f  = tid + NTH * r;
            int o  = f >> 2;              // owner thread (step o*4+k)
            int mq = f & 3;               // float4 within the step's 64B
            float4 v = make_float4(s_out[(mq*4+0)*257 + o],
                                   s_out[(mq*4+1)*257 + o],
                                   s_out[(mq*4+2)*257 + o],
                                   s_out[(mq*4+3)*257 + o]);
            out4[(size_t)o * 16 + k * 4 + mq] = v;
        }
        __syncthreads();
    }
}

extern "C" void kernel_launch(void* const* d_in, const int* in_sizes, int n_in,
                              void* d_out, int out_size) {
    const float* in = (const float*)d_in[0];
    float* out = (float*)d_out;
    int Bn = in_sizes[0] / (T_LEN * 6);   // 512 for the reference shapes
    cudaFuncSetAttribute(preint_kernel,
                         cudaFuncAttributeMaxDynamicSharedMemorySize, SMEM_BYTES);
    preint_kernel<<<Bn * SPLIT, NTH, SMEM_BYTES>>>(in, out);
}